// round 12
// baseline (speedup 1.0000x reference)
#include <cuda_runtime.h>
#include <cuda_fp16.h>
#include <cstdint>
#include <cstddef>

// ============================================================================
// Problem constants
// ============================================================================
#define N_TOK 4096
#define DIM   1024

// ---- fp16 mma.sync m16n8k16 GEMM config: 256x128 CTA tile, 64x64 warp tile ----
#define BM 256
#define BN 128
#define BKH 64                         // fp16 elems per K-stage (128 B/row)
#define LDH 72                         // padded smem row stride in halves (144 B)
#define TILE_A_H (BM * LDH)            // 18432 halves
#define TILE_B_H (BN * LDH)            // 9216 halves
#define BUF_H  (TILE_A_H + TILE_B_H)   // 27648 halves per stage
#define NSTAGE 3
#define SMEM_H (NSTAGE * BUF_H * 2)    // 165888 bytes

// ============================================================================
// Device scratch (fp16 planes; __device__ globals per allocation-free rule)
// ============================================================================
static __device__ __align__(256) __half g_tx  [N_TOK * DIM];
static __device__ __align__(256) __half g_im  [N_TOK * DIM];
static __device__ __align__(256) __half g_wt  [DIM * DIM];
static __device__ __align__(256) __half g_wi  [DIM * DIM];
static __device__ __align__(256) __half g_imT [DIM * N_TOK];
static __device__ __align__(256) __half g_txT [DIM * N_TOK];
static __device__ __align__(256) __half g_t   [N_TOK * DIM];
static __device__ __align__(256) __half g_i   [N_TOK * DIM];
static __device__ __align__(256) __half g_P   [(size_t)N_TOK * N_TOK];
static __device__ __align__(256) __half g_PT  [(size_t)N_TOK * N_TOK];
static __device__ __align__(256) float  g_rowsum[N_TOK];
static __device__ __align__(256) float  g_colsum[N_TOK];

// ============================================================================
// Helpers
// ============================================================================
__device__ __forceinline__ void cp_async16(void* dst_smem, const void* src) {
    uint32_t dst;
    asm("{ .reg .u64 t; cvta.to.shared.u64 t, %1; cvt.u32.u64 %0, t; }" : "=r"(dst) : "l"(dst_smem));
    asm volatile("cp.async.cg.shared.global [%0], [%1], 16;" :: "r"(dst), "l"(src) : "memory");
}
#define CP_COMMIT() asm volatile("cp.async.commit_group;" ::: "memory")
#define CP_WAIT(n)  asm volatile("cp.async.wait_group %0;" :: "n"(n) : "memory")

__device__ __forceinline__ uint32_t smem_addr32(const void* p) {
    uint32_t a;
    asm("{ .reg .u64 t; cvta.to.shared.u64 t, %1; cvt.u32.u64 %0, t; }" : "=r"(a) : "l"(p));
    return a;
}

__device__ __forceinline__ void ldsm_x4(uint32_t& r0, uint32_t& r1, uint32_t& r2, uint32_t& r3,
                                        uint32_t addr) {
    asm volatile("ldmatrix.sync.aligned.m8n8.x4.shared.b16 {%0,%1,%2,%3}, [%4];"
                 : "=r"(r0), "=r"(r1), "=r"(r2), "=r"(r3) : "r"(addr));
}

__device__ __forceinline__ void mma_f16(float& d0, float& d1, float& d2, float& d3,
                                        uint32_t a0, uint32_t a1, uint32_t a2, uint32_t a3,
                                        uint32_t b0, uint32_t b1) {
    asm volatile(
        "mma.sync.aligned.m16n8k16.row.col.f32.f16.f16.f32 "
        "{%0,%1,%2,%3}, {%4,%5,%6,%7}, {%8,%9}, {%0,%1,%2,%3};"
        : "+f"(d0), "+f"(d1), "+f"(d2), "+f"(d3)
        : "r"(a0), "r"(a1), "r"(a2), "r"(a3), "r"(b0), "r"(b1));
}

// ============================================================================
// fp16 GEMM:  D[m,n] = sum_k A[m,k] * B[n,k]   (NT, both K-major, fp32 accum)
// 256x128 CTA tile, 8 warps in 4x2 grid (64x64 warp tile), 3-stage cp.async
// pipeline, ONE __syncthreads per K-chunk. blockIdx.z selects pointer set.
// MODE 0: C[m,n] = h(D + bias[n])                           (projections, fp16 out)
// MODE 1: e = h(exp(D/32)); C[m,n]=e; C2[n,m]=e             (logits -> P, P^T, fp16)
// MODE 2: Cf[m,n] = D * scale[0] / denom[m]                 (attn @ V, fp32 out)
// ============================================================================
template <int MODE>
__global__ __launch_bounds__(256, 1)
void gemm_h(const __half* __restrict__ A0, const __half* __restrict__ B0,
            const __half* __restrict__ A1, const __half* __restrict__ B1,
            int K, int ldA, int ldB,
            __half* __restrict__ C0h, __half* __restrict__ C1h, int ldC,
            __half* __restrict__ C2, int ldC2,
            float* __restrict__ Cf0, float* __restrict__ Cf1,
            const float* __restrict__ bias0, const float* __restrict__ bias1,
            const float* __restrict__ denom0, const float* __restrict__ denom1,
            const float* __restrict__ scale0p, const float* __restrict__ scale1p)
{
    extern __shared__ __half smemh[];
    const int z   = blockIdx.z;
    const __half* __restrict__ A = z ? A1 : A0;
    const __half* __restrict__ B = z ? B1 : B0;
    __half* __restrict__ C       = z ? C1h : C0h;
    float*  __restrict__ Cf      = z ? Cf1 : Cf0;
    const float* __restrict__ bias  = z ? bias1  : bias0;
    const float* __restrict__ denom = z ? denom1 : denom0;
    const float* __restrict__ scale = z ? scale1p : scale0p;

    const int tid = threadIdx.x;
    const int wid = tid >> 5;
    const int lid = tid & 31;
    const int mw  = wid >> 1;       // 0..3 -> 64 rows each
    const int nw  = wid & 1;        // 0..1 -> 64 cols each
    const int m0  = blockIdx.y * BM;
    const int n0  = blockIdx.x * BN;

    const __half* __restrict__ Ab = A + (size_t)m0 * ldA;
    const __half* __restrict__ Bb = B + (size_t)n0 * ldB;

    const uint32_t sbase = smem_addr32(smemh);

    // 64x64 warp tile: acc[i 0..3 (m16)][j 0..7 (n8)][4]
    float acc[4][8][4];
    #pragma unroll
    for (int i = 0; i < 4; i++)
        #pragma unroll
        for (int j = 0; j < 8; j++)
            #pragma unroll
            for (int c = 0; c < 4; c++) acc[i][j][c] = 0.0f;

    const int NK = K / BKH;

    auto fill = [&](int kt) {
        const int bufI = kt % NSTAGE;
        const int kofs = kt * BKH;
        char* base = (char*)smemh + (size_t)bufI * BUF_H * 2;
        #pragma unroll
        for (int i = 0; i < 12; i++) {
            const int idx = tid + i * 256;        // 0..3071 16B-chunks
            const int isB = (idx >= 2048);
            const int cc  = isB ? (idx - 2048) : idx;
            const int row = cc >> 3;              // A: 0..255, B: 0..127
            const int ch  = cc & 7;               // 16B chunk (8 halves)
            const __half* src = (isB ? (Bb + (size_t)row * ldB) : (Ab + (size_t)row * ldA))
                                + kofs + ch * 8;
            char* dst = base + (isB ? TILE_A_H * 2 : 0) + row * (LDH * 2) + ch * 16;
            cp_async16(dst, src);
        }
        CP_COMMIT();
    };

    // Prologue: fill NSTAGE-1 = 2 stages.
    fill(0);
    if (NK > 1) fill(1);

    // per-lane ldmatrix address offsets (bytes)
    const uint32_t a_lane = (uint32_t)(((lid & 15) * LDH + (lid >> 4) * 8) * 2);
    const uint32_t b_lane = (uint32_t)((((lid & 7) + ((lid >> 4) << 3)) * LDH
                                        + ((lid >> 3) & 1) * 8) * 2);

    for (int kt = 0; kt < NK; kt++) {
        const int b = kt % NSTAGE;
        if (kt + 1 < NK) { CP_WAIT(1); } else { CP_WAIT(0); }
        __syncthreads();    // fill(kt) visible; all warps done reading stage (kt+2)%3

        // Write stage (kt+2)%3 — the stage read at iter kt-1; safe after the barrier.
        if (kt + 2 < NK) fill(kt + 2);

        const uint32_t Abase = sbase + (uint32_t)(b * BUF_H * 2)
                             + (uint32_t)(mw * 64 * LDH * 2) + a_lane;
        const uint32_t Bbase = sbase + (uint32_t)(b * BUF_H * 2) + (uint32_t)(TILE_A_H * 2)
                             + (uint32_t)(nw * 64 * LDH * 2) + b_lane;

        #pragma unroll
        for (int ks = 0; ks < 4; ks++) {
            const uint32_t kb = (uint32_t)(ks * 16 * 2);
            uint32_t af[4][4];
            #pragma unroll
            for (int i = 0; i < 4; i++)
                ldsm_x4(af[i][0], af[i][1], af[i][2], af[i][3],
                        Abase + (uint32_t)(i * 16 * LDH * 2) + kb);
            uint32_t bf[8][2];
            #pragma unroll
            for (int jj = 0; jj < 4; jj++)
                ldsm_x4(bf[jj * 2][0], bf[jj * 2][1], bf[jj * 2 + 1][0], bf[jj * 2 + 1][1],
                        Bbase + (uint32_t)(jj * 16 * LDH * 2) + kb);
            #pragma unroll
            for (int i = 0; i < 4; i++)
                #pragma unroll
                for (int j = 0; j < 8; j++)
                    mma_f16(acc[i][j][0], acc[i][j][1], acc[i][j][2], acc[i][j][3],
                            af[i][0], af[i][1], af[i][2], af[i][3],
                            bf[j][0], bf[j][1]);
        }
    }

    // ---------------- Epilogue ----------------
    // Thread values: rows m0+mw*64+i*16+{g, g+8}, cols n0+nw*64+j*8+{2q, 2q+1}
    const int g = lid >> 2;
    const int q = lid & 3;
    const float sc_glob = (MODE == 2) ? scale[0] : 0.0f;
    __half* bufT = smemh;     // MODE 1 transpose staging: [128 n][260 m] halves
    if (MODE == 1) __syncthreads();   // all warps done with mainloop smem before reuse

    #pragma unroll
    for (int i = 0; i < 4; i++) {
        const int r0 = mw * 64 + i * 16 + g;
        const int r1 = r0 + 8;
        float sc0 = 1.0f, sc1 = 1.0f;
        if (MODE == 2) {
            sc0 = sc_glob / __ldg(&denom[m0 + r0]);
            sc1 = sc_glob / __ldg(&denom[m0 + r1]);
        }
        #pragma unroll
        for (int j = 0; j < 8; j++) {
            const int c0 = nw * 64 + j * 8 + 2 * q;
            float v00 = acc[i][j][0], v01 = acc[i][j][1];
            float v10 = acc[i][j][2], v11 = acc[i][j][3];
            if (MODE == 0) {
                const float b0 = __ldg(&bias[n0 + c0]);
                const float b1 = __ldg(&bias[n0 + c0 + 1]);
                __half2 h0 = __floats2half2_rn(v00 + b0, v01 + b1);
                __half2 h1 = __floats2half2_rn(v10 + b0, v11 + b1);
                *(__half2*)(C + (size_t)(m0 + r0) * ldC + n0 + c0) = h0;
                *(__half2*)(C + (size_t)(m0 + r1) * ldC + n0 + c0) = h1;
            } else if (MODE == 1) {
                __half2 h0 = __floats2half2_rn(__expf(v00 * 0.03125f), __expf(v01 * 0.03125f));
                __half2 h1 = __floats2half2_rn(__expf(v10 * 0.03125f), __expf(v11 * 0.03125f));
                *(__half2*)(C + (size_t)(m0 + r0) * ldC + n0 + c0) = h0;
                *(__half2*)(C + (size_t)(m0 + r1) * ldC + n0 + c0) = h1;
                bufT[(c0    ) * 260 + r0] = __low2half(h0);
                bufT[(c0 + 1) * 260 + r0] = __high2half(h0);
                bufT[(c0    ) * 260 + r1] = __low2half(h1);
                bufT[(c0 + 1) * 260 + r1] = __high2half(h1);
            } else {
                float2 f0 = make_float2(v00 * sc0, v01 * sc0);
                float2 f1 = make_float2(v10 * sc1, v11 * sc1);
                *(float2*)(Cf + (size_t)(m0 + r0) * ldC + n0 + c0) = f0;
                *(float2*)(Cf + (size_t)(m0 + r1) * ldC + n0 + c0) = f1;
            }
        }
    }

    if (MODE == 1) {
        __syncthreads();
        // coalesced P^T stores: warp w handles n-rows [w*16, w*16+16), 256 m each
        for (int r = wid * 16; r < wid * 16 + 16; r++) {
            uint32_t* dst32 = (uint32_t*)(C2 + (size_t)(n0 + r) * ldC2 + m0);
            const uint32_t* src32 = (const uint32_t*)(bufT + r * 260);
            dst32[lid]      = src32[lid];
            dst32[lid + 32] = src32[lid + 32];
            dst32[lid + 64] = src32[lid + 64];
            dst32[lid + 96] = src32[lid + 96];
        }
    }
}

// ============================================================================
// Helper kernels
// ============================================================================
// Fused: fp32 -> fp16 plane AND fp16 transposed plane; z selects text/image.
__global__ void convtrans2_k(const float* __restrict__ in0, __half* __restrict__ out0,
                             __half* __restrict__ out0T,
                             const float* __restrict__ in1, __half* __restrict__ out1,
                             __half* __restrict__ out1T, int rows, int cols) {
    __shared__ float t[32][33];
    const float* in = blockIdx.z ? in1 : in0;
    __half* out     = blockIdx.z ? out1 : out0;
    __half* outT    = blockIdx.z ? out1T : out0T;
    const int x0 = blockIdx.x * 32, y0 = blockIdx.y * 32;
    for (int j = threadIdx.y; j < 32; j += 8) {
        float v = in[(size_t)(y0 + j) * cols + x0 + threadIdx.x];
        t[j][threadIdx.x] = v;
        out[(size_t)(y0 + j) * cols + x0 + threadIdx.x] = __float2half_rn(v);
    }
    __syncthreads();
    for (int j = threadIdx.y; j < 32; j += 8)
        outT[(size_t)(x0 + j) * rows + y0 + threadIdx.x] = __float2half_rn(t[threadIdx.x][j]);
}

// Merged fp32->fp16 for both weight matrices (blockIdx.y selects).
__global__ void tohalf2_k(const float4* __restrict__ in0, __half2* __restrict__ out0,
                          const float4* __restrict__ in1, __half2* __restrict__ out1, int n4) {
    int i = blockIdx.x * blockDim.x + threadIdx.x;
    const float4* in = blockIdx.y ? in1 : in0;
    __half2* out     = blockIdx.y ? out1 : out0;
    if (i < n4) {
        float4 a = in[i];
        out[2 * i]     = __floats2half2_rn(a.x, a.y);
        out[2 * i + 1] = __floats2half2_rn(a.z, a.w);
    }
}

// Merged rowsum over P (y=0 -> rs) and PT (y=1 -> cs).
__global__ void rowsum_h2_k(const __half2* __restrict__ P0, float* __restrict__ out0,
                            const __half2* __restrict__ P1, float* __restrict__ out1,
                            int ncols) {
    __shared__ float red[256];
    const __half2* P2 = blockIdx.y ? P1 : P0;
    float* out        = blockIdx.y ? out1 : out0;
    const __half2* row = P2 + (size_t)blockIdx.x * (ncols / 2);
    float s = 0.0f;
    for (int j = threadIdx.x; j < ncols / 2; j += 256) {
        float2 v = __half22float2(row[j]);
        s += v.x + v.y;
    }
    red[threadIdx.x] = s;
    __syncthreads();
    for (int o = 128; o > 0; o >>= 1) {
        if (threadIdx.x < o) red[threadIdx.x] += red[threadIdx.x + o];
        __syncthreads();
    }
    if (threadIdx.x == 0) out[blockIdx.x] = red[0];
}

// ============================================================================
// Host launch
// ============================================================================
extern "C" void kernel_launch(void* const* d_in, const int* in_sizes, int n_in,
                              void* d_out, int out_size) {
    const float* text    = (const float*)d_in[0];
    const float* image   = (const float*)d_in[1];
    const float* w_text  = (const float*)d_in[2];
    const float* b_text  = (const float*)d_in[3];
    const float* w_image = (const float*)d_in[4];
    const float* b_image = (const float*)d_in[5];
    const float* s_TI    = (const float*)d_in[6];
    const float* s_IT    = (const float*)d_in[7];
    float* out = (float*)d_out;

    __half *tx, *im, *wt, *wi, *imT, *txT, *th, *ih, *P, *PT;
    float *rs, *cs;
    cudaGetSymbolAddress((void**)&tx,  g_tx);
    cudaGetSymbolAddress((void**)&im,  g_im);
    cudaGetSymbolAddress((void**)&wt,  g_wt);
    cudaGetSymbolAddress((void**)&wi,  g_wi);
    cudaGetSymbolAddress((void**)&imT, g_imT);
    cudaGetSymbolAddress((void**)&txT, g_txT);
    cudaGetSymbolAddress((void**)&th,  g_t);
    cudaGetSymbolAddress((void**)&ih,  g_i);
    cudaGetSymbolAddress((void**)&P,   g_P);
    cudaGetSymbolAddress((void**)&PT,  g_PT);
    cudaGetSymbolAddress((void**)&rs,  g_rowsum);
    cudaGetSymbolAddress((void**)&cs,  g_colsum);

    cudaFuncSetAttribute((const void*)gemm_h<0>, cudaFuncAttributeMaxDynamicSharedMemorySize, SMEM_H);
    cudaFuncSetAttribute((const void*)gemm_h<1>, cudaFuncAttributeMaxDynamicSharedMemorySize, SMEM_H);
    cudaFuncSetAttribute((const void*)gemm_h<2>, cudaFuncAttributeMaxDynamicSharedMemorySize, SMEM_H);

    // 1) fused fp16 conversion + transpose for text / image (single launch)
    {
        dim3 blk(32, 8);
        dim3 grd(DIM / 32, N_TOK / 32, 2);
        convtrans2_k<<<grd, blk>>>(text, tx, txT, image, im, imT, N_TOK, DIM);
    }
    // 2) weights -> fp16 (merged)
    {
        int w4 = DIM * DIM / 4;
        dim3 grd((w4 + 255) / 256, 2);
        tohalf2_k<<<grd, 256>>>((const float4*)w_text,  (__half2*)wt,
                                (const float4*)w_image, (__half2*)wi, w4);
    }
    // 3) projections merged:  t = text@wt^T+b_t (z=0),  i = image@wi^T+b_i (z=1)
    {
        dim3 grd(DIM / BN, N_TOK / BM, 2);
        gemm_h<0><<<grd, 256, SMEM_H>>>(tx, wt, im, wi, DIM, DIM, DIM,
                                        th, ih, DIM, nullptr, 0,
                                        nullptr, nullptr,
                                        b_text, b_image, nullptr, nullptr, nullptr, nullptr);
    }
    // 4) logits + exp:  P = exp((t @ i^T)/32),  PT = P^T
    {
        dim3 grd(N_TOK / BN, N_TOK / BM, 1);
        gemm_h<1><<<grd, 256, SMEM_H>>>(th, ih, th, ih, DIM, DIM, DIM,
                                        P, P, N_TOK, PT, N_TOK,
                                        nullptr, nullptr,
                                        nullptr, nullptr, nullptr, nullptr, nullptr, nullptr);
    }
    // 5) softmax denominators (merged)
    {
        dim3 grd(N_TOK, 2);
        rowsum_h2_k<<<grd, 256>>>((const __half2*)P, rs, (const __half2*)PT, cs, N_TOK);
    }
    // 6) outputs merged: out1 = (P@image)*s_TI/rs (z=0), out2 = (PT@text)*s_IT/cs (z=1)
    {
        dim3 grd(DIM / BN, N_TOK / BM, 2);
        gemm_h<2><<<grd, 256, SMEM_H>>>(P, imT, PT, txT, N_TOK, N_TOK, N_TOK,
                                        nullptr, nullptr, DIM, nullptr, 0,
                                        out, out + (size_t)N_TOK * DIM,
                                        nullptr, nullptr, rs, cs, s_TI, s_IT);
    }
}

// round 13
// speedup vs baseline: 1.1328x; 1.1328x over previous
#include <cuda_runtime.h>
#include <cuda_fp16.h>
#include <cstdint>
#include <cstddef>

// ============================================================================
// Problem constants
// ============================================================================
#define N_TOK 4096
#define DIM   1024

// ---- fp16 mma.sync m16n8k16 GEMM config (R10 config: 128x128, 64x32 warps) ----
#define BM 128
#define BN 128
#define BKH 64                        // fp16 elems per K-stage (128 B/row)
#define LDH 72                        // padded smem row stride in halves (144 B)
#define TILE_H (128 * LDH)            // halves per tile (A or B)
#define BUF_H  (2 * TILE_H)           // A + B halves per stage
#define NSTAGE 3
#define SMEM_H (NSTAGE * BUF_H * 2)   // bytes = 110592

#define NTILE_N (N_TOK / BN)          // 32 partial tiles per row
#define NTILE_M (N_TOK / BM)          // 32 partial tiles per col

// ============================================================================
// Device scratch (fp16 planes; __device__ globals per allocation-free rule)
// ============================================================================
static __device__ __align__(256) __half g_tx  [N_TOK * DIM];
static __device__ __align__(256) __half g_im  [N_TOK * DIM];
static __device__ __align__(256) __half g_wt  [DIM * DIM];
static __device__ __align__(256) __half g_wi  [DIM * DIM];
static __device__ __align__(256) __half g_imT [DIM * N_TOK];
static __device__ __align__(256) __half g_txT [DIM * N_TOK];
static __device__ __align__(256) __half g_t   [N_TOK * DIM];
static __device__ __align__(256) __half g_i   [N_TOK * DIM];
static __device__ __align__(256) __half g_P   [(size_t)N_TOK * N_TOK];
static __device__ __align__(256) __half g_PT  [(size_t)N_TOK * N_TOK];
static __device__ __align__(256) float  g_prs [N_TOK * NTILE_N];   // partial row sums
static __device__ __align__(256) float  g_pcs [N_TOK * NTILE_M];   // partial col sums
static __device__ __align__(256) float  g_rowsum[N_TOK];
static __device__ __align__(256) float  g_colsum[N_TOK];

// ============================================================================
// Helpers
// ============================================================================
__device__ __forceinline__ void cp_async16(void* dst_smem, const void* src) {
    uint32_t dst;
    asm("{ .reg .u64 t; cvta.to.shared.u64 t, %1; cvt.u32.u64 %0, t; }" : "=r"(dst) : "l"(dst_smem));
    asm volatile("cp.async.cg.shared.global [%0], [%1], 16;" :: "r"(dst), "l"(src) : "memory");
}
#define CP_COMMIT() asm volatile("cp.async.commit_group;" ::: "memory")
#define CP_WAIT(n)  asm volatile("cp.async.wait_group %0;" :: "n"(n) : "memory")

__device__ __forceinline__ uint32_t smem_addr32(const void* p) {
    uint32_t a;
    asm("{ .reg .u64 t; cvta.to.shared.u64 t, %1; cvt.u32.u64 %0, t; }" : "=r"(a) : "l"(p));
    return a;
}

__device__ __forceinline__ void ldsm_x4(uint32_t& r0, uint32_t& r1, uint32_t& r2, uint32_t& r3,
                                        uint32_t addr) {
    asm volatile("ldmatrix.sync.aligned.m8n8.x4.shared.b16 {%0,%1,%2,%3}, [%4];"
                 : "=r"(r0), "=r"(r1), "=r"(r2), "=r"(r3) : "r"(addr));
}

__device__ __forceinline__ void mma_f16(float& d0, float& d1, float& d2, float& d3,
                                        uint32_t a0, uint32_t a1, uint32_t a2, uint32_t a3,
                                        uint32_t b0, uint32_t b1) {
    asm volatile(
        "mma.sync.aligned.m16n8k16.row.col.f32.f16.f16.f32 "
        "{%0,%1,%2,%3}, {%4,%5,%6,%7}, {%8,%9}, {%0,%1,%2,%3};"
        : "+f"(d0), "+f"(d1), "+f"(d2), "+f"(d3)
        : "r"(a0), "r"(a1), "r"(a2), "r"(a3), "r"(b0), "r"(b1));
}

// ============================================================================
// fp16 GEMM:  D[m,n] = sum_k A[m,k] * B[n,k]   (NT, both K-major, fp32 accum)
// 3-stage cp.async pipeline, ONE __syncthreads per K-chunk. (R10 core.)
// blockIdx.z in {0,1} selects pointer set (merged independent GEMMs).
// MODE 0: C[m,n] = h(D + bias[n])                           (projections, fp16 out)
// MODE 1: e = h(exp(D/32)); C[m,n]=e; C2[n,m]=e; partial row/col sums -> prs/pcs
// MODE 2: Cf[m,n] = D * scale[0] / denom[m]                 (attn @ V, fp32 out)
// ============================================================================
template <int MODE>
__global__ __launch_bounds__(256, 2)
void gemm_h(const __half* __restrict__ A0, const __half* __restrict__ B0,
            const __half* __restrict__ A1, const __half* __restrict__ B1,
            int K, int ldA, int ldB,
            __half* __restrict__ C0h, __half* __restrict__ C1h, int ldC,
            __half* __restrict__ C2, int ldC2,
            float* __restrict__ Cf0, float* __restrict__ Cf1,
            const float* __restrict__ bias0, const float* __restrict__ bias1,
            const float* __restrict__ denom0, const float* __restrict__ denom1,
            const float* __restrict__ scale0p, const float* __restrict__ scale1p,
            float* __restrict__ prs, float* __restrict__ pcs)
{
    extern __shared__ __half smemh[];
    const int z   = blockIdx.z;
    const __half* __restrict__ A = z ? A1 : A0;
    const __half* __restrict__ B = z ? B1 : B0;
    __half* __restrict__ C       = z ? C1h : C0h;
    float*  __restrict__ Cf      = z ? Cf1 : Cf0;
    const float* __restrict__ bias  = z ? bias1  : bias0;
    const float* __restrict__ denom = z ? denom1 : denom0;
    const float* __restrict__ scale = z ? scale1p : scale0p;

    const int tid = threadIdx.x;
    const int wid = tid >> 5;
    const int lid = tid & 31;
    const int mw  = wid >> 2;       // 0..1 -> 64 rows
    const int nw  = wid & 3;        // 0..3 -> 32 cols
    const int m0  = blockIdx.y * BM;
    const int n0  = blockIdx.x * BN;

    const __half* __restrict__ Ab = A + (size_t)m0 * ldA;
    const __half* __restrict__ Bb = B + (size_t)n0 * ldB;

    const uint32_t sbase = smem_addr32(smemh);

    float acc[4][4][4];
    #pragma unroll
    for (int i = 0; i < 4; i++)
        #pragma unroll
        for (int j = 0; j < 4; j++)
            #pragma unroll
            for (int c = 0; c < 4; c++) acc[i][j][c] = 0.0f;

    const int NK = K / BKH;

    auto fill = [&](int kt) {
        const int bufI = kt % NSTAGE;
        const int kofs = kt * BKH;
        char* base = (char*)smemh + bufI * BUF_H * 2;
        #pragma unroll
        for (int i = 0; i < 8; i++) {
            const int idx = tid + i * 256;        // 0..2047 16B-chunks
            const int isB = idx >> 10;
            const int cc  = idx & 1023;
            const int row = cc >> 3;              // 0..127
            const int ch  = cc & 7;               // 16B chunk (8 halves)
            const __half* src = (isB ? (Bb + (size_t)row * ldB) : (Ab + (size_t)row * ldA))
                                + kofs + ch * 8;
            char* dst = base + (isB ? TILE_H * 2 : 0) + row * (LDH * 2) + ch * 16;
            cp_async16(dst, src);
        }
        CP_COMMIT();
    };

    // Prologue: fill NSTAGE-1 = 2 stages.
    fill(0);
    if (NK > 1) fill(1);

    // per-lane ldmatrix address offsets (bytes)
    const uint32_t a_lane = (uint32_t)(((lid & 15) * LDH + (lid >> 4) * 8) * 2);
    const uint32_t b_lane = (uint32_t)((((lid & 7) + ((lid >> 4) << 3)) * LDH
                                        + ((lid >> 3) & 1) * 8) * 2);

    for (int kt = 0; kt < NK; kt++) {
        const int b = kt % NSTAGE;
        if (kt + 1 < NK) { CP_WAIT(1); } else { CP_WAIT(0); }
        __syncthreads();    // fill(kt) visible; all warps done reading stage (kt+2)%3

        // Write stage (kt+2)%3 — the stage read at iter kt-1; safe after the barrier.
        if (kt + 2 < NK) fill(kt + 2);

        const uint32_t Abase = sbase + (uint32_t)(b * BUF_H * 2) + (uint32_t)(mw * 64 * LDH * 2);
        const uint32_t Bbase = sbase + (uint32_t)(b * BUF_H * 2) + (uint32_t)(TILE_H * 2)
                             + (uint32_t)(nw * 32 * LDH * 2);

        #pragma unroll
        for (int ks = 0; ks < 4; ks++) {
            const uint32_t kb = (uint32_t)(ks * 16 * 2);
            uint32_t af[4][4];
            #pragma unroll
            for (int i = 0; i < 4; i++)
                ldsm_x4(af[i][0], af[i][1], af[i][2], af[i][3],
                        Abase + (uint32_t)(i * 16 * LDH * 2) + kb + a_lane);
            uint32_t bf[4][2];
            #pragma unroll
            for (int jj = 0; jj < 2; jj++)
                ldsm_x4(bf[jj * 2][0], bf[jj * 2][1], bf[jj * 2 + 1][0], bf[jj * 2 + 1][1],
                        Bbase + (uint32_t)(jj * 16 * LDH * 2) + kb + b_lane);
            #pragma unroll
            for (int i = 0; i < 4; i++)
                #pragma unroll
                for (int j = 0; j < 4; j++)
                    mma_f16(acc[i][j][0], acc[i][j][1], acc[i][j][2], acc[i][j][3],
                            af[i][0], af[i][1], af[i][2], af[i][3],
                            bf[j][0], bf[j][1]);
        }
    }

    // ---------------- Epilogue ----------------
    // Thread values: rows m0+mw*64+i*16+{g, g+8}, cols n0+nw*32+j*8+{2q, 2q+1}
    const int g = lid >> 2;
    const int q = lid & 3;
    const float sc_glob = (MODE == 2) ? scale[0] : 0.0f;
    __half* bufT  = smemh;                              // [128 n][132 m] halves
    float*  bufRS = (float*)(smemh + 16896);            // [128 rows][4 nw]
    float*  bufCS = bufRS + 128 * 4;                    // [128 cols][2 mw]
    if (MODE == 1) __syncthreads();   // all warps done with mainloop smem before reuse

    #pragma unroll
    for (int i = 0; i < 4; i++) {
        const int r0 = mw * 64 + i * 16 + g;
        const int r1 = r0 + 8;
        float sc0 = 1.0f, sc1 = 1.0f;
        if (MODE == 2) {
            sc0 = sc_glob / __ldg(&denom[m0 + r0]);
            sc1 = sc_glob / __ldg(&denom[m0 + r1]);
        }
        #pragma unroll
        for (int j = 0; j < 4; j++) {
            const int c0 = nw * 32 + j * 8 + 2 * q;
            float v00 = acc[i][j][0], v01 = acc[i][j][1];
            float v10 = acc[i][j][2], v11 = acc[i][j][3];
            if (MODE == 0) {
                const float b0 = __ldg(&bias[n0 + c0]);
                const float b1 = __ldg(&bias[n0 + c0 + 1]);
                __half2 h0 = __floats2half2_rn(v00 + b0, v01 + b1);
                __half2 h1 = __floats2half2_rn(v10 + b0, v11 + b1);
                *(__half2*)(C + (size_t)(m0 + r0) * ldC + n0 + c0) = h0;
                *(__half2*)(C + (size_t)(m0 + r1) * ldC + n0 + c0) = h1;
            } else if (MODE == 1) {
                __half2 h0 = __floats2half2_rn(__expf(v00 * 0.03125f), __expf(v01 * 0.03125f));
                __half2 h1 = __floats2half2_rn(__expf(v10 * 0.03125f), __expf(v11 * 0.03125f));
                *(__half2*)(C + (size_t)(m0 + r0) * ldC + n0 + c0) = h0;
                *(__half2*)(C + (size_t)(m0 + r1) * ldC + n0 + c0) = h1;
                bufT[(c0    ) * 132 + r0] = __low2half(h0);
                bufT[(c0 + 1) * 132 + r0] = __high2half(h0);
                bufT[(c0    ) * 132 + r1] = __low2half(h1);
                bufT[(c0 + 1) * 132 + r1] = __high2half(h1);
            } else {
                float2 f0 = make_float2(v00 * sc0, v01 * sc0);
                float2 f1 = make_float2(v10 * sc1, v11 * sc1);
                *(float2*)(Cf + (size_t)(m0 + r0) * ldC + n0 + c0) = f0;
                *(float2*)(Cf + (size_t)(m0 + r1) * ldC + n0 + c0) = f1;
            }
        }
    }

    if (MODE == 1) {
        // ---- partial softmax sums (recomputed unrounded exp from live acc) ----
        // row partials: reduce over this warp's 32 cols (lanes sharing g: xor 1,2)
        #pragma unroll
        for (int i = 0; i < 4; i++) {
            float s0 = 0.0f, s1 = 0.0f;
            #pragma unroll
            for (int j = 0; j < 4; j++) {
                s0 += __expf(acc[i][j][0] * 0.03125f) + __expf(acc[i][j][1] * 0.03125f);
                s1 += __expf(acc[i][j][2] * 0.03125f) + __expf(acc[i][j][3] * 0.03125f);
            }
            s0 += __shfl_xor_sync(0xFFFFFFFFu, s0, 1);
            s0 += __shfl_xor_sync(0xFFFFFFFFu, s0, 2);
            s1 += __shfl_xor_sync(0xFFFFFFFFu, s1, 1);
            s1 += __shfl_xor_sync(0xFFFFFFFFu, s1, 2);
            if (q == 0) {
                bufRS[(mw * 64 + i * 16 + g) * 4 + nw]     = s0;
                bufRS[(mw * 64 + i * 16 + g + 8) * 4 + nw] = s1;
            }
        }
        // col partials: reduce over this warp's 64 rows (lanes sharing q: xor 4,8,16)
        #pragma unroll
        for (int j = 0; j < 4; j++)
            #pragma unroll
            for (int h = 0; h < 2; h++) {
                float s = 0.0f;
                #pragma unroll
                for (int i = 0; i < 4; i++)
                    s += __expf(acc[i][j][h] * 0.03125f) + __expf(acc[i][j][h + 2] * 0.03125f);
                s += __shfl_xor_sync(0xFFFFFFFFu, s, 4);
                s += __shfl_xor_sync(0xFFFFFFFFu, s, 8);
                s += __shfl_xor_sync(0xFFFFFFFFu, s, 16);
                if (g == 0)
                    bufCS[(nw * 32 + j * 8 + 2 * q + h) * 2 + mw] = s;
            }

        __syncthreads();
        // coalesced P^T stores: warp w handles n-rows [w*16, w*16+16)
        for (int r = wid * 16; r < wid * 16 + 16; r++) {
            uint32_t* dst32 = (uint32_t*)(C2 + (size_t)(n0 + r) * ldC2 + m0);
            const uint32_t* src32 = (const uint32_t*)(bufT + r * 132);
            dst32[lid]      = src32[lid];
            dst32[lid + 32] = src32[lid + 32];
        }
        // global partial-sum stores
        if (tid < 128) {
            const int r = tid;
            float s = bufRS[r * 4] + bufRS[r * 4 + 1] + bufRS[r * 4 + 2] + bufRS[r * 4 + 3];
            prs[(size_t)(m0 + r) * NTILE_N + blockIdx.x] = s;
        } else {
            const int c = tid - 128;
            pcs[(size_t)(n0 + c) * NTILE_M + blockIdx.y] = bufCS[c * 2] + bufCS[c * 2 + 1];
        }
    }
}

// ============================================================================
// Helper kernels
// ============================================================================
// Fused: fp32 -> fp16 plane AND fp16 transposed plane; z selects text/image.
// 64x64 tile, float2 loads, __half2 stores on both sides.
__global__ void convtrans2_k(const float* __restrict__ in0, __half* __restrict__ out0,
                             __half* __restrict__ out0T,
                             const float* __restrict__ in1, __half* __restrict__ out1,
                             __half* __restrict__ out1T, int rows, int cols) {
    __shared__ float t[64][65];
    const float* in = blockIdx.z ? in1 : in0;
    __half* out     = blockIdx.z ? out1 : out0;
    __half* outT    = blockIdx.z ? out1T : out0T;
    const int x0 = blockIdx.x * 64, y0 = blockIdx.y * 64;
    const int tx = threadIdx.x;     // 0..31
    const int ty = threadIdx.y;     // 0..7
    #pragma unroll
    for (int j = 0; j < 64; j += 8) {
        const int rl = ty + j;
        float2 v = *(const float2*)(in + (size_t)(y0 + rl) * cols + x0 + 2 * tx);
        t[rl][2 * tx]     = v.x;
        t[rl][2 * tx + 1] = v.y;
        *(__half2*)(out + (size_t)(y0 + rl) * cols + x0 + 2 * tx) = __floats2half2_rn(v.x, v.y);
    }
    __syncthreads();
    #pragma unroll
    for (int j = 0; j < 64; j += 8) {
        const int cl = ty + j;
        __half2 hv = __floats2half2_rn(t[2 * tx][cl], t[2 * tx + 1][cl]);
        *(__half2*)(outT + (size_t)(x0 + cl) * rows + y0 + 2 * tx) = hv;
    }
}

// Merged fp32->fp16 for both weight matrices (blockIdx.y selects).
__global__ void tohalf2_k(const float4* __restrict__ in0, __half2* __restrict__ out0,
                          const float4* __restrict__ in1, __half2* __restrict__ out1, int n4) {
    int i = blockIdx.x * blockDim.x + threadIdx.x;
    const float4* in = blockIdx.y ? in1 : in0;
    __half2* out     = blockIdx.y ? out1 : out0;
    if (i < n4) {
        float4 a = in[i];
        out[2 * i]     = __floats2half2_rn(a.x, a.y);
        out[2 * i + 1] = __floats2half2_rn(a.z, a.w);
    }
}

// Finalize: rs[r] = sum of 32 row partials; cs[c] = sum of 32 col partials.
__global__ void finalize_k(const float* __restrict__ prs, const float* __restrict__ pcs,
                           float* __restrict__ rs, float* __restrict__ cs) {
    const int i = blockIdx.x * 256 + threadIdx.x;    // 0..8191
    const float* src = (i < N_TOK) ? (prs + (size_t)i * NTILE_N)
                                   : (pcs + (size_t)(i - N_TOK) * NTILE_M);
    float s = 0.0f;
    #pragma unroll
    for (int k = 0; k < NTILE_N; k++) s += src[k];
    if (i < N_TOK) rs[i] = s;
    else           cs[i - N_TOK] = s;
}

// ============================================================================
// Host launch
// ============================================================================
extern "C" void kernel_launch(void* const* d_in, const int* in_sizes, int n_in,
                              void* d_out, int out_size) {
    const float* text    = (const float*)d_in[0];
    const float* image   = (const float*)d_in[1];
    const float* w_text  = (const float*)d_in[2];
    const float* b_text  = (const float*)d_in[3];
    const float* w_image = (const float*)d_in[4];
    const float* b_image = (const float*)d_in[5];
    const float* s_TI    = (const float*)d_in[6];
    const float* s_IT    = (const float*)d_in[7];
    float* out = (float*)d_out;

    __half *tx, *im, *wt, *wi, *imT, *txT, *th, *ih, *P, *PT;
    float *prs, *pcs, *rs, *cs;
    cudaGetSymbolAddress((void**)&tx,  g_tx);
    cudaGetSymbolAddress((void**)&im,  g_im);
    cudaGetSymbolAddress((void**)&wt,  g_wt);
    cudaGetSymbolAddress((void**)&wi,  g_wi);
    cudaGetSymbolAddress((void**)&imT, g_imT);
    cudaGetSymbolAddress((void**)&txT, g_txT);
    cudaGetSymbolAddress((void**)&th,  g_t);
    cudaGetSymbolAddress((void**)&ih,  g_i);
    cudaGetSymbolAddress((void**)&P,   g_P);
    cudaGetSymbolAddress((void**)&PT,  g_PT);
    cudaGetSymbolAddress((void**)&prs, g_prs);
    cudaGetSymbolAddress((void**)&pcs, g_pcs);
    cudaGetSymbolAddress((void**)&rs,  g_rowsum);
    cudaGetSymbolAddress((void**)&cs,  g_colsum);

    cudaFuncSetAttribute((const void*)gemm_h<0>, cudaFuncAttributeMaxDynamicSharedMemorySize, SMEM_H);
    cudaFuncSetAttribute((const void*)gemm_h<1>, cudaFuncAttributeMaxDynamicSharedMemorySize, SMEM_H);
    cudaFuncSetAttribute((const void*)gemm_h<2>, cudaFuncAttributeMaxDynamicSharedMemorySize, SMEM_H);

    // 1) fused fp16 conversion + transpose for text / image (single launch)
    {
        dim3 blk(32, 8);
        dim3 grd(DIM / 64, N_TOK / 64, 2);
        convtrans2_k<<<grd, blk>>>(text, tx, txT, image, im, imT, N_TOK, DIM);
    }
    // 2) weights -> fp16 (merged)
    {
        int w4 = DIM * DIM / 4;
        dim3 grd((w4 + 255) / 256, 2);
        tohalf2_k<<<grd, 256>>>((const float4*)w_text,  (__half2*)wt,
                                (const float4*)w_image, (__half2*)wi, w4);
    }
    // 3) projections merged:  t = text@wt^T+b_t (z=0),  i = image@wi^T+b_i (z=1)
    {
        dim3 grd(DIM / BN, N_TOK / BM, 2);
        gemm_h<0><<<grd, 256, SMEM_H>>>(tx, wt, im, wi, DIM, DIM, DIM,
                                        th, ih, DIM, nullptr, 0,
                                        nullptr, nullptr,
                                        b_text, b_image, nullptr, nullptr, nullptr, nullptr,
                                        nullptr, nullptr);
    }
    // 4) logits + exp:  P = exp((t @ i^T)/32),  PT = P^T, partial sums -> prs/pcs
    {
        dim3 grd(N_TOK / BN, N_TOK / BM, 1);
        gemm_h<1><<<grd, 256, SMEM_H>>>(th, ih, th, ih, DIM, DIM, DIM,
                                        P, P, N_TOK, PT, N_TOK,
                                        nullptr, nullptr,
                                        nullptr, nullptr, nullptr, nullptr, nullptr, nullptr,
                                        prs, pcs);
    }
    // 5) finalize softmax denominators (1 MB read)
    finalize_k<<<(2 * N_TOK) / 256, 256>>>(prs, pcs, rs, cs);
    // 6) outputs merged: out1 = (P@image)*s_TI/rs (z=0), out2 = (PT@text)*s_IT/cs (z=1)
    {
        dim3 grd(DIM / BN, N_TOK / BM, 2);
        gemm_h<2><<<grd, 256, SMEM_H>>>(P, imT, PT, txT, N_TOK, N_TOK, N_TOK,
                                        nullptr, nullptr, DIM, nullptr, 0,
                                        out, out + (size_t)N_TOK * DIM,
                                        nullptr, nullptr, rs, cs, s_TI, s_IT,
                                        nullptr, nullptr);
    }
}

// round 14
// speedup vs baseline: 1.1424x; 1.0085x over previous
#include <cuda_runtime.h>
#include <cuda_fp16.h>
#include <cstdint>
#include <cstddef>

// ============================================================================
// Problem constants
// ============================================================================
#define N_TOK 4096
#define DIM   1024

// ---- fp16 mma.sync m16n8k16: 128x128 CTA tile, 4 warps, 64x64 warp tile ----
#define BM 128
#define BN 128
#define BKH 64                        // fp16 elems per K-stage (128 B/row)
#define LDH 72                        // padded smem row stride in halves (144 B)
#define TILE_H (128 * LDH)            // halves per tile (A or B)
#define BUF_H  (2 * TILE_H)           // A + B halves per stage
#define NSTAGE 3
#define SMEM_H (NSTAGE * BUF_H * 2)   // bytes = 110592  (2 CTAs = 221184 <= 228KB)

#define NTILE_N (N_TOK / BN)          // 32 partial tiles per row
#define NTILE_M (N_TOK / BM)          // 32 partial tiles per col

// ============================================================================
// Device scratch (fp16 planes; __device__ globals per allocation-free rule)
// ============================================================================
static __device__ __align__(256) __half g_tx  [N_TOK * DIM];
static __device__ __align__(256) __half g_im  [N_TOK * DIM];
static __device__ __align__(256) __half g_wt  [DIM * DIM];
static __device__ __align__(256) __half g_wi  [DIM * DIM];
static __device__ __align__(256) __half g_imT [DIM * N_TOK];
static __device__ __align__(256) __half g_txT [DIM * N_TOK];
static __device__ __align__(256) __half g_t   [N_TOK * DIM];
static __device__ __align__(256) __half g_i   [N_TOK * DIM];
static __device__ __align__(256) __half g_P   [(size_t)N_TOK * N_TOK];
static __device__ __align__(256) __half g_PT  [(size_t)N_TOK * N_TOK];
static __device__ __align__(256) float  g_prs [N_TOK * NTILE_N];   // partial row sums
static __device__ __align__(256) float  g_pcs [N_TOK * NTILE_M];   // partial col sums
static __device__ __align__(256) float  g_rowsum[N_TOK];
static __device__ __align__(256) float  g_colsum[N_TOK];

// ============================================================================
// Helpers
// ============================================================================
__device__ __forceinline__ void cp_async16(void* dst_smem, const void* src) {
    uint32_t dst;
    asm("{ .reg .u64 t; cvta.to.shared.u64 t, %1; cvt.u32.u64 %0, t; }" : "=r"(dst) : "l"(dst_smem));
    asm volatile("cp.async.cg.shared.global [%0], [%1], 16;" :: "r"(dst), "l"(src) : "memory");
}
#define CP_COMMIT() asm volatile("cp.async.commit_group;" ::: "memory")
#define CP_WAIT(n)  asm volatile("cp.async.wait_group %0;" :: "n"(n) : "memory")

__device__ __forceinline__ uint32_t smem_addr32(const void* p) {
    uint32_t a;
    asm("{ .reg .u64 t; cvta.to.shared.u64 t, %1; cvt.u32.u64 %0, t; }" : "=r"(a) : "l"(p));
    return a;
}

__device__ __forceinline__ void ldsm_x4(uint32_t& r0, uint32_t& r1, uint32_t& r2, uint32_t& r3,
                                        uint32_t addr) {
    asm volatile("ldmatrix.sync.aligned.m8n8.x4.shared.b16 {%0,%1,%2,%3}, [%4];"
                 : "=r"(r0), "=r"(r1), "=r"(r2), "=r"(r3) : "r"(addr));
}

__device__ __forceinline__ void mma_f16(float& d0, float& d1, float& d2, float& d3,
                                        uint32_t a0, uint32_t a1, uint32_t a2, uint32_t a3,
                                        uint32_t b0, uint32_t b1) {
    asm volatile(
        "mma.sync.aligned.m16n8k16.row.col.f32.f16.f16.f32 "
        "{%0,%1,%2,%3}, {%4,%5,%6,%7}, {%8,%9}, {%0,%1,%2,%3};"
        : "+f"(d0), "+f"(d1), "+f"(d2), "+f"(d3)
        : "r"(a0), "r"(a1), "r"(a2), "r"(a3), "r"(b0), "r"(b1));
}

// ============================================================================
// fp16 GEMM:  D[m,n] = sum_k A[m,k] * B[n,k]   (NT, both K-major, fp32 accum)
// 128x128 CTA tile, 4 warps in 2x2 grid (64x64 warp tiles), 3-stage cp.async
// pipeline, ONE __syncthreads per K-chunk, 2 CTAs/SM. blockIdx.z selects set.
// MODE 0: C[m,n] = h(D + bias[n])                           (projections, fp16 out)
// MODE 1: e = h(exp(D/32)); C[m,n]=e; C2[n,m]=e; partial row/col sums -> prs/pcs
// MODE 2: Cf[m,n] = D * scale[0] / denom[m]                 (attn @ V, fp32 out)
// ============================================================================
template <int MODE>
__global__ __launch_bounds__(128, 2)
void gemm_h(const __half* __restrict__ A0, const __half* __restrict__ B0,
            const __half* __restrict__ A1, const __half* __restrict__ B1,
            int K, int ldA, int ldB,
            __half* __restrict__ C0h, __half* __restrict__ C1h, int ldC,
            __half* __restrict__ C2, int ldC2,
            float* __restrict__ Cf0, float* __restrict__ Cf1,
            const float* __restrict__ bias0, const float* __restrict__ bias1,
            const float* __restrict__ denom0, const float* __restrict__ denom1,
            const float* __restrict__ scale0p, const float* __restrict__ scale1p,
            float* __restrict__ prs, float* __restrict__ pcs)
{
    extern __shared__ __half smemh[];
    const int z   = blockIdx.z;
    const __half* __restrict__ A = z ? A1 : A0;
    const __half* __restrict__ B = z ? B1 : B0;
    __half* __restrict__ C       = z ? C1h : C0h;
    float*  __restrict__ Cf      = z ? Cf1 : Cf0;
    const float* __restrict__ bias  = z ? bias1  : bias0;
    const float* __restrict__ denom = z ? denom1 : denom0;
    const float* __restrict__ scale = z ? scale1p : scale0p;

    const int tid = threadIdx.x;
    const int wid = tid >> 5;       // 0..3
    const int lid = tid & 31;
    const int mw  = wid >> 1;       // 0..1 -> 64 rows
    const int nw  = wid & 1;        // 0..1 -> 64 cols
    const int m0  = blockIdx.y * BM;
    const int n0  = blockIdx.x * BN;

    const __half* __restrict__ Ab = A + (size_t)m0 * ldA;
    const __half* __restrict__ Bb = B + (size_t)n0 * ldB;

    const uint32_t sbase = smem_addr32(smemh);

    // 64x64 warp tile: acc[i 0..3 (m16)][j 0..7 (n8)][4]
    float acc[4][8][4];
    #pragma unroll
    for (int i = 0; i < 4; i++)
        #pragma unroll
        for (int j = 0; j < 8; j++)
            #pragma unroll
            for (int c = 0; c < 4; c++) acc[i][j][c] = 0.0f;

    const int NK = K / BKH;

    auto fill = [&](int kt) {
        const int bufI = kt % NSTAGE;
        const int kofs = kt * BKH;
        char* base = (char*)smemh + bufI * BUF_H * 2;
        #pragma unroll
        for (int i = 0; i < 16; i++) {
            const int idx = tid + i * 128;        // 0..2047 16B-chunks
            const int isB = idx >> 10;
            const int cc  = idx & 1023;
            const int row = cc >> 3;              // 0..127
            const int ch  = cc & 7;               // 16B chunk (8 halves)
            const __half* src = (isB ? (Bb + (size_t)row * ldB) : (Ab + (size_t)row * ldA))
                                + kofs + ch * 8;
            char* dst = base + (isB ? TILE_H * 2 : 0) + row * (LDH * 2) + ch * 16;
            cp_async16(dst, src);
        }
        CP_COMMIT();
    };

    // Prologue: fill NSTAGE-1 = 2 stages.
    fill(0);
    if (NK > 1) fill(1);

    // per-lane ldmatrix address offsets (bytes)
    const uint32_t a_lane = (uint32_t)(((lid & 15) * LDH + (lid >> 4) * 8) * 2);
    const uint32_t b_lane = (uint32_t)((((lid & 7) + ((lid >> 4) << 3)) * LDH
                                        + ((lid >> 3) & 1) * 8) * 2);

    for (int kt = 0; kt < NK; kt++) {
        const int b = kt % NSTAGE;
        if (kt + 1 < NK) { CP_WAIT(1); } else { CP_WAIT(0); }
        __syncthreads();    // fill(kt) visible; all warps done reading stage (kt+2)%3

        // Write stage (kt+2)%3 — the stage read at iter kt-1; safe after the barrier.
        if (kt + 2 < NK) fill(kt + 2);

        const uint32_t Abase = sbase + (uint32_t)(b * BUF_H * 2)
                             + (uint32_t)(mw * 64 * LDH * 2) + a_lane;
        const uint32_t Bbase = sbase + (uint32_t)(b * BUF_H * 2) + (uint32_t)(TILE_H * 2)
                             + (uint32_t)(nw * 64 * LDH * 2) + b_lane;

        #pragma unroll
        for (int ks = 0; ks < 4; ks++) {
            const uint32_t kb = (uint32_t)(ks * 16 * 2);
            uint32_t af[4][4];
            #pragma unroll
            for (int i = 0; i < 4; i++)
                ldsm_x4(af[i][0], af[i][1], af[i][2], af[i][3],
                        Abase + (uint32_t)(i * 16 * LDH * 2) + kb);
            uint32_t bf[8][2];
            #pragma unroll
            for (int jj = 0; jj < 4; jj++)
                ldsm_x4(bf[jj * 2][0], bf[jj * 2][1], bf[jj * 2 + 1][0], bf[jj * 2 + 1][1],
                        Bbase + (uint32_t)(jj * 16 * LDH * 2) + kb);
            #pragma unroll
            for (int i = 0; i < 4; i++)
                #pragma unroll
                for (int j = 0; j < 8; j++)
                    mma_f16(acc[i][j][0], acc[i][j][1], acc[i][j][2], acc[i][j][3],
                            af[i][0], af[i][1], af[i][2], af[i][3],
                            bf[j][0], bf[j][1]);
        }
    }

    // ---------------- Epilogue ----------------
    // Thread values: rows m0+mw*64+i*16+{g, g+8}, cols n0+nw*64+j*8+{2q, 2q+1}
    const int g = lid >> 2;
    const int q = lid & 3;
    const float sc_glob = (MODE == 2) ? scale[0] : 0.0f;
    __half* bufT  = smemh;                              // [128 n][132 m] halves
    float*  bufRS = (float*)(smemh + 16896);            // [128 rows][2 nw]
    float*  bufCS = bufRS + 128 * 2;                    // [128 cols][2 mw]
    if (MODE == 1) __syncthreads();   // all warps done with mainloop smem before reuse

    #pragma unroll
    for (int i = 0; i < 4; i++) {
        const int r0 = mw * 64 + i * 16 + g;
        const int r1 = r0 + 8;
        float sc0 = 1.0f, sc1 = 1.0f;
        if (MODE == 2) {
            sc0 = sc_glob / __ldg(&denom[m0 + r0]);
            sc1 = sc_glob / __ldg(&denom[m0 + r1]);
        }
        #pragma unroll
        for (int j = 0; j < 8; j++) {
            const int c0 = nw * 64 + j * 8 + 2 * q;
            float v00 = acc[i][j][0], v01 = acc[i][j][1];
            float v10 = acc[i][j][2], v11 = acc[i][j][3];
            if (MODE == 0) {
                const float b0 = __ldg(&bias[n0 + c0]);
                const float b1 = __ldg(&bias[n0 + c0 + 1]);
                __half2 h0 = __floats2half2_rn(v00 + b0, v01 + b1);
                __half2 h1 = __floats2half2_rn(v10 + b0, v11 + b1);
                *(__half2*)(C + (size_t)(m0 + r0) * ldC + n0 + c0) = h0;
                *(__half2*)(C + (size_t)(m0 + r1) * ldC + n0 + c0) = h1;
            } else if (MODE == 1) {
                __half2 h0 = __floats2half2_rn(__expf(v00 * 0.03125f), __expf(v01 * 0.03125f));
                __half2 h1 = __floats2half2_rn(__expf(v10 * 0.03125f), __expf(v11 * 0.03125f));
                *(__half2*)(C + (size_t)(m0 + r0) * ldC + n0 + c0) = h0;
                *(__half2*)(C + (size_t)(m0 + r1) * ldC + n0 + c0) = h1;
                bufT[(c0    ) * 132 + r0] = __low2half(h0);
                bufT[(c0 + 1) * 132 + r0] = __high2half(h0);
                bufT[(c0    ) * 132 + r1] = __low2half(h1);
                bufT[(c0 + 1) * 132 + r1] = __high2half(h1);
            } else {
                float2 f0 = make_float2(v00 * sc0, v01 * sc0);
                float2 f1 = make_float2(v10 * sc1, v11 * sc1);
                *(float2*)(Cf + (size_t)(m0 + r0) * ldC + n0 + c0) = f0;
                *(float2*)(Cf + (size_t)(m0 + r1) * ldC + n0 + c0) = f1;
            }
        }
    }

    if (MODE == 1) {
        // ---- partial softmax sums (recomputed unrounded exp from live acc) ----
        // row partials: this warp covers 64 cols; lanes sharing a row: xor 1,2 (q)
        #pragma unroll
        for (int i = 0; i < 4; i++) {
            float s0 = 0.0f, s1 = 0.0f;
            #pragma unroll
            for (int j = 0; j < 8; j++) {
                s0 += __expf(acc[i][j][0] * 0.03125f) + __expf(acc[i][j][1] * 0.03125f);
                s1 += __expf(acc[i][j][2] * 0.03125f) + __expf(acc[i][j][3] * 0.03125f);
            }
            s0 += __shfl_xor_sync(0xFFFFFFFFu, s0, 1);
            s0 += __shfl_xor_sync(0xFFFFFFFFu, s0, 2);
            s1 += __shfl_xor_sync(0xFFFFFFFFu, s1, 1);
            s1 += __shfl_xor_sync(0xFFFFFFFFu, s1, 2);
            if (q == 0) {
                bufRS[(mw * 64 + i * 16 + g) * 2 + nw]     = s0;
                bufRS[(mw * 64 + i * 16 + g + 8) * 2 + nw] = s1;
            }
        }
        // col partials: this warp covers 64 rows; lanes sharing a col: xor 4,8,16 (g)
        #pragma unroll
        for (int j = 0; j < 8; j++)
            #pragma unroll
            for (int h = 0; h < 2; h++) {
                float s = 0.0f;
                #pragma unroll
                for (int i = 0; i < 4; i++)
                    s += __expf(acc[i][j][h] * 0.03125f) + __expf(acc[i][j][h + 2] * 0.03125f);
                s += __shfl_xor_sync(0xFFFFFFFFu, s, 4);
                s += __shfl_xor_sync(0xFFFFFFFFu, s, 8);
                s += __shfl_xor_sync(0xFFFFFFFFu, s, 16);
                if (g == 0)
                    bufCS[(nw * 64 + j * 8 + 2 * q + h) * 2 + mw] = s;
            }

        __syncthreads();
        // coalesced P^T stores: warp w handles n-rows [w*32, w*32+32)
        for (int r = wid * 32; r < wid * 32 + 32; r++) {
            uint32_t* dst32 = (uint32_t*)(C2 + (size_t)(n0 + r) * ldC2 + m0);
            const uint32_t* src32 = (const uint32_t*)(bufT + r * 132);
            dst32[lid]      = src32[lid];
            dst32[lid + 32] = src32[lid + 32];
        }
        // global partial-sum stores (128 threads: each does one row AND one col)
        {
            const int r = tid;
            prs[(size_t)(m0 + r) * NTILE_N + blockIdx.x] = bufRS[r * 2] + bufRS[r * 2 + 1];
            pcs[(size_t)(n0 + r) * NTILE_M + blockIdx.y] = bufCS[r * 2] + bufCS[r * 2 + 1];
        }
    }
}

// ============================================================================
// Helper kernels
// ============================================================================
// Fused: fp32 -> fp16 plane AND fp16 transposed plane; z selects text/image.
__global__ void convtrans2_k(const float* __restrict__ in0, __half* __restrict__ out0,
                             __half* __restrict__ out0T,
                             const float* __restrict__ in1, __half* __restrict__ out1,
                             __half* __restrict__ out1T, int rows, int cols) {
    __shared__ float t[64][65];
    const float* in = blockIdx.z ? in1 : in0;
    __half* out     = blockIdx.z ? out1 : out0;
    __half* outT    = blockIdx.z ? out1T : out0T;
    const int x0 = blockIdx.x * 64, y0 = blockIdx.y * 64;
    const int tx = threadIdx.x;     // 0..31
    const int ty = threadIdx.y;     // 0..7
    #pragma unroll
    for (int j = 0; j < 64; j += 8) {
        const int rl = ty + j;
        float2 v = *(const float2*)(in + (size_t)(y0 + rl) * cols + x0 + 2 * tx);
        t[rl][2 * tx]     = v.x;
        t[rl][2 * tx + 1] = v.y;
        *(__half2*)(out + (size_t)(y0 + rl) * cols + x0 + 2 * tx) = __floats2half2_rn(v.x, v.y);
    }
    __syncthreads();
    #pragma unroll
    for (int j = 0; j < 64; j += 8) {
        const int cl = ty + j;
        __half2 hv = __floats2half2_rn(t[2 * tx][cl], t[2 * tx + 1][cl]);
        *(__half2*)(outT + (size_t)(x0 + cl) * rows + y0 + 2 * tx) = hv;
    }
}

// Merged fp32->fp16 for both weight matrices (blockIdx.y selects).
__global__ void tohalf2_k(const float4* __restrict__ in0, __half2* __restrict__ out0,
                          const float4* __restrict__ in1, __half2* __restrict__ out1, int n4) {
    int i = blockIdx.x * blockDim.x + threadIdx.x;
    const float4* in = blockIdx.y ? in1 : in0;
    __half2* out     = blockIdx.y ? out1 : out0;
    if (i < n4) {
        float4 a = in[i];
        out[2 * i]     = __floats2half2_rn(a.x, a.y);
        out[2 * i + 1] = __floats2half2_rn(a.z, a.w);
    }
}

// Finalize: rs[r] = sum of 32 row partials; cs[c] = sum of 32 col partials.
__global__ void finalize_k(const float* __restrict__ prs, const float* __restrict__ pcs,
                           float* __restrict__ rs, float* __restrict__ cs) {
    const int i = blockIdx.x * 256 + threadIdx.x;    // 0..8191
    const float* src = (i < N_TOK) ? (prs + (size_t)i * NTILE_N)
                                   : (pcs + (size_t)(i - N_TOK) * NTILE_M);
    float s = 0.0f;
    #pragma unroll
    for (int k = 0; k < NTILE_N; k++) s += src[k];
    if (i < N_TOK) rs[i] = s;
    else           cs[i - N_TOK] = s;
}

// ============================================================================
// Host launch
// ============================================================================
extern "C" void kernel_launch(void* const* d_in, const int* in_sizes, int n_in,
                              void* d_out, int out_size) {
    const float* text    = (const float*)d_in[0];
    const float* image   = (const float*)d_in[1];
    const float* w_text  = (const float*)d_in[2];
    const float* b_text  = (const float*)d_in[3];
    const float* w_image = (const float*)d_in[4];
    const float* b_image = (const float*)d_in[5];
    const float* s_TI    = (const float*)d_in[6];
    const float* s_IT    = (const float*)d_in[7];
    float* out = (float*)d_out;

    __half *tx, *im, *wt, *wi, *imT, *txT, *th, *ih, *P, *PT;
    float *prs, *pcs, *rs, *cs;
    cudaGetSymbolAddress((void**)&tx,  g_tx);
    cudaGetSymbolAddress((void**)&im,  g_im);
    cudaGetSymbolAddress((void**)&wt,  g_wt);
    cudaGetSymbolAddress((void**)&wi,  g_wi);
    cudaGetSymbolAddress((void**)&imT, g_imT);
    cudaGetSymbolAddress((void**)&txT, g_txT);
    cudaGetSymbolAddress((void**)&th,  g_t);
    cudaGetSymbolAddress((void**)&ih,  g_i);
    cudaGetSymbolAddress((void**)&P,   g_P);
    cudaGetSymbolAddress((void**)&PT,  g_PT);
    cudaGetSymbolAddress((void**)&prs, g_prs);
    cudaGetSymbolAddress((void**)&pcs, g_pcs);
    cudaGetSymbolAddress((void**)&rs,  g_rowsum);
    cudaGetSymbolAddress((void**)&cs,  g_colsum);

    cudaFuncSetAttribute((const void*)gemm_h<0>, cudaFuncAttributeMaxDynamicSharedMemorySize, SMEM_H);
    cudaFuncSetAttribute((const void*)gemm_h<1>, cudaFuncAttributeMaxDynamicSharedMemorySize, SMEM_H);
    cudaFuncSetAttribute((const void*)gemm_h<2>, cudaFuncAttributeMaxDynamicSharedMemorySize, SMEM_H);

    // 1) fused fp16 conversion + transpose for text / image (single launch)
    {
        dim3 blk(32, 8);
        dim3 grd(DIM / 64, N_TOK / 64, 2);
        convtrans2_k<<<grd, blk>>>(text, tx, txT, image, im, imT, N_TOK, DIM);
    }
    // 2) weights -> fp16 (merged)
    {
        int w4 = DIM * DIM / 4;
        dim3 grd((w4 + 255) / 256, 2);
        tohalf2_k<<<grd, 256>>>((const float4*)w_text,  (__half2*)wt,
                                (const float4*)w_image, (__half2*)wi, w4);
    }
    // 3) projections merged:  t = text@wt^T+b_t (z=0),  i = image@wi^T+b_i (z=1)
    {
        dim3 grd(DIM / BN, N_TOK / BM, 2);
        gemm_h<0><<<grd, 128, SMEM_H>>>(tx, wt, im, wi, DIM, DIM, DIM,
                                        th, ih, DIM, nullptr, 0,
                                        nullptr, nullptr,
                                        b_text, b_image, nullptr, nullptr, nullptr, nullptr,
                                        nullptr, nullptr);
    }
    // 4) logits + exp:  P = exp((t @ i^T)/32),  PT = P^T, partial sums -> prs/pcs
    {
        dim3 grd(N_TOK / BN, N_TOK / BM, 1);
        gemm_h<1><<<grd, 128, SMEM_H>>>(th, ih, th, ih, DIM, DIM, DIM,
                                        P, P, N_TOK, PT, N_TOK,
                                        nullptr, nullptr,
                                        nullptr, nullptr, nullptr, nullptr, nullptr, nullptr,
                                        prs, pcs);
    }
    // 5) finalize softmax denominators (1 MB read)
    finalize_k<<<(2 * N_TOK) / 256, 256>>>(prs, pcs, rs, cs);
    // 6) outputs merged: out1 = (P@image)*s_TI/rs (z=0), out2 = (PT@text)*s_IT/cs (z=1)
    {
        dim3 grd(DIM / BN, N_TOK / BM, 2);
        gemm_h<2><<<grd, 128, SMEM_H>>>(P, imT, PT, txT, N_TOK, N_TOK, N_TOK,
                                        nullptr, nullptr, DIM, nullptr, 0,
                                        out, out + (size_t)N_TOK * DIM,
                                        nullptr, nullptr, rs, cs, s_TI, s_IT,
                                        nullptr, nullptr);
    }
}

// round 15
// speedup vs baseline: 1.1492x; 1.0060x over previous
#include <cuda_runtime.h>
#include <cuda_fp16.h>
#include <cstdint>
#include <cstddef>

// ============================================================================
// Problem constants
// ============================================================================
#define N_TOK 4096
#define DIM   1024

// ---- fp16 mma.sync m16n8k16: 128x128 CTA tile, 4 warps, 64x64 warp tile ----
#define BM 128
#define BN 128
#define BKH 64                        // fp16 elems per K-stage (128 B/row)
#define LDH 72                        // padded smem row stride in halves (144 B)
#define TILE_H (128 * LDH)            // halves per tile (A or B)
#define BUF_H  (2 * TILE_H)           // A + B halves per stage
#define NSTAGE 3
#define SMEM_H (NSTAGE * BUF_H * 2)   // bytes = 110592  (2 CTAs = 221184 <= 228KB)

#define NTILE_N (N_TOK / BN)          // 32 partial tiles per row
#define NTILE_M (N_TOK / BM)          // 32 partial tiles per col

// ============================================================================
// Device scratch (fp16 planes; __device__ globals per allocation-free rule)
// ============================================================================
static __device__ __align__(256) __half g_tx  [N_TOK * DIM];
static __device__ __align__(256) __half g_im  [N_TOK * DIM];
static __device__ __align__(256) __half g_wt  [DIM * DIM];
static __device__ __align__(256) __half g_wi  [DIM * DIM];
static __device__ __align__(256) __half g_imT [DIM * N_TOK];
static __device__ __align__(256) __half g_txT [DIM * N_TOK];
static __device__ __align__(256) __half g_t   [N_TOK * DIM];
static __device__ __align__(256) __half g_i   [N_TOK * DIM];
static __device__ __align__(256) __half g_P   [(size_t)N_TOK * N_TOK];
static __device__ __align__(256) __half g_PT  [(size_t)N_TOK * N_TOK];
static __device__ __align__(256) float  g_prs [N_TOK * NTILE_N];   // partial row sums
static __device__ __align__(256) float  g_pcs [N_TOK * NTILE_M];   // partial col sums

// ============================================================================
// Helpers
// ============================================================================
__device__ __forceinline__ void cp_async16(void* dst_smem, const void* src) {
    uint32_t dst;
    asm("{ .reg .u64 t; cvta.to.shared.u64 t, %1; cvt.u32.u64 %0, t; }" : "=r"(dst) : "l"(dst_smem));
    asm volatile("cp.async.cg.shared.global [%0], [%1], 16;" :: "r"(dst), "l"(src) : "memory");
}
#define CP_COMMIT() asm volatile("cp.async.commit_group;" ::: "memory")
#define CP_WAIT(n)  asm volatile("cp.async.wait_group %0;" :: "n"(n) : "memory")

__device__ __forceinline__ uint32_t smem_addr32(const void* p) {
    uint32_t a;
    asm("{ .reg .u64 t; cvta.to.shared.u64 t, %1; cvt.u32.u64 %0, t; }" : "=r"(a) : "l"(p));
    return a;
}

__device__ __forceinline__ void ldsm_x4(uint32_t& r0, uint32_t& r1, uint32_t& r2, uint32_t& r3,
                                        uint32_t addr) {
    asm volatile("ldmatrix.sync.aligned.m8n8.x4.shared.b16 {%0,%1,%2,%3}, [%4];"
                 : "=r"(r0), "=r"(r1), "=r"(r2), "=r"(r3) : "r"(addr));
}

__device__ __forceinline__ void mma_f16(float& d0, float& d1, float& d2, float& d3,
                                        uint32_t a0, uint32_t a1, uint32_t a2, uint32_t a3,
                                        uint32_t b0, uint32_t b1) {
    asm volatile(
        "mma.sync.aligned.m16n8k16.row.col.f32.f16.f16.f32 "
        "{%0,%1,%2,%3}, {%4,%5,%6,%7}, {%8,%9}, {%0,%1,%2,%3};"
        : "+f"(d0), "+f"(d1), "+f"(d2), "+f"(d3)
        : "r"(a0), "r"(a1), "r"(a2), "r"(a3), "r"(b0), "r"(b1));
}

// ============================================================================
// fp16 GEMM:  D[m,n] = sum_k A[m,k] * B[n,k]   (NT, both K-major, fp32 accum)
// 128x128 CTA tile, 4 warps in 2x2 grid (64x64 warp tiles), 3-stage cp.async
// pipeline, ONE __syncthreads per K-chunk, 2 CTAs/SM. blockIdx.z selects set.
// MODE 0: C[m,n] = h(D + bias[n])                           (projections, fp16 out)
// MODE 1: e = h(exp(D/32)); C[m,n]=e; C2[n,m]=e; partial row/col sums -> prs/pcs
// MODE 2: Cf[m,n] = D * scale[0] / denom[m]; denom computed in-kernel from parts
// ============================================================================
template <int MODE>
__global__ __launch_bounds__(128, 2)
void gemm_h(const __half* __restrict__ A0, const __half* __restrict__ B0,
            const __half* __restrict__ A1, const __half* __restrict__ B1,
            int K, int ldA, int ldB,
            __half* __restrict__ C0h, __half* __restrict__ C1h, int ldC,
            __half* __restrict__ C2, int ldC2,
            float* __restrict__ Cf0, float* __restrict__ Cf1,
            const float* __restrict__ bias0, const float* __restrict__ bias1,
            const float* __restrict__ part0, const float* __restrict__ part1,
            const float* __restrict__ scale0p, const float* __restrict__ scale1p,
            float* __restrict__ prs, float* __restrict__ pcs)
{
    extern __shared__ __half smemh[];
    const int z   = blockIdx.z;
    const __half* __restrict__ A = z ? A1 : A0;
    const __half* __restrict__ B = z ? B1 : B0;
    __half* __restrict__ C       = z ? C1h : C0h;
    float*  __restrict__ Cf      = z ? Cf1 : Cf0;
    const float* __restrict__ bias  = z ? bias1  : bias0;
    const float* __restrict__ part  = z ? part1  : part0;   // MODE 2: partial sums
    const float* __restrict__ scale = z ? scale1p : scale0p;

    const int tid = threadIdx.x;
    const int wid = tid >> 5;       // 0..3
    const int lid = tid & 31;
    const int mw  = wid >> 1;       // 0..1 -> 64 rows
    const int nw  = wid & 1;        // 0..1 -> 64 cols
    const int m0  = blockIdx.y * BM;
    const int n0  = blockIdx.x * BN;

    const __half* __restrict__ Ab = A + (size_t)m0 * ldA;
    const __half* __restrict__ Bb = B + (size_t)n0 * ldB;

    const uint32_t sbase = smem_addr32(smemh);

    // 64x64 warp tile: acc[i 0..3 (m16)][j 0..7 (n8)][4]
    float acc[4][8][4];
    #pragma unroll
    for (int i = 0; i < 4; i++)
        #pragma unroll
        for (int j = 0; j < 8; j++)
            #pragma unroll
            for (int c = 0; c < 4; c++) acc[i][j][c] = 0.0f;

    const int NK = K / BKH;

    auto fill = [&](int kt) {
        const int bufI = kt % NSTAGE;
        const int kofs = kt * BKH;
        char* base = (char*)smemh + bufI * BUF_H * 2;
        #pragma unroll
        for (int i = 0; i < 16; i++) {
            const int idx = tid + i * 128;        // 0..2047 16B-chunks
            const int isB = idx >> 10;
            const int cc  = idx & 1023;
            const int row = cc >> 3;              // 0..127
            const int ch  = cc & 7;               // 16B chunk (8 halves)
            const __half* src = (isB ? (Bb + (size_t)row * ldB) : (Ab + (size_t)row * ldA))
                                + kofs + ch * 8;
            char* dst = base + (isB ? TILE_H * 2 : 0) + row * (LDH * 2) + ch * 16;
            cp_async16(dst, src);
        }
        CP_COMMIT();
    };

    // Prologue: fill NSTAGE-1 = 2 stages.
    fill(0);
    if (NK > 1) fill(1);

    // per-lane ldmatrix address offsets (bytes)
    const uint32_t a_lane = (uint32_t)(((lid & 15) * LDH + (lid >> 4) * 8) * 2);
    const uint32_t b_lane = (uint32_t)((((lid & 7) + ((lid >> 4) << 3)) * LDH
                                        + ((lid >> 3) & 1) * 8) * 2);

    for (int kt = 0; kt < NK; kt++) {
        const int b = kt % NSTAGE;
        if (kt + 1 < NK) { CP_WAIT(1); } else { CP_WAIT(0); }
        __syncthreads();    // fill(kt) visible; all warps done reading stage (kt+2)%3

        // Write stage (kt+2)%3 — the stage read at iter kt-1; safe after the barrier.
        if (kt + 2 < NK) fill(kt + 2);

        const uint32_t Abase = sbase + (uint32_t)(b * BUF_H * 2)
                             + (uint32_t)(mw * 64 * LDH * 2) + a_lane;
        const uint32_t Bbase = sbase + (uint32_t)(b * BUF_H * 2) + (uint32_t)(TILE_H * 2)
                             + (uint32_t)(nw * 64 * LDH * 2) + b_lane;

        #pragma unroll
        for (int ks = 0; ks < 4; ks++) {
            const uint32_t kb = (uint32_t)(ks * 16 * 2);
            uint32_t af[4][4];
            #pragma unroll
            for (int i = 0; i < 4; i++)
                ldsm_x4(af[i][0], af[i][1], af[i][2], af[i][3],
                        Abase + (uint32_t)(i * 16 * LDH * 2) + kb);
            uint32_t bf[8][2];
            #pragma unroll
            for (int jj = 0; jj < 4; jj++)
                ldsm_x4(bf[jj * 2][0], bf[jj * 2][1], bf[jj * 2 + 1][0], bf[jj * 2 + 1][1],
                        Bbase + (uint32_t)(jj * 16 * LDH * 2) + kb);
            #pragma unroll
            for (int i = 0; i < 4; i++)
                #pragma unroll
                for (int j = 0; j < 8; j++)
                    mma_f16(acc[i][j][0], acc[i][j][1], acc[i][j][2], acc[i][j][3],
                            af[i][0], af[i][1], af[i][2], af[i][3],
                            bf[j][0], bf[j][1]);
        }
    }

    // ---------------- Epilogue ----------------
    // Thread values: rows m0+mw*64+i*16+{g, g+8}, cols n0+nw*64+j*8+{2q, 2q+1}
    const int g = lid >> 2;
    const int q = lid & 3;
    const float sc_glob = (MODE == 2) ? scale[0] : 0.0f;
    __half* bufT  = smemh;                              // [128 n][132 m] halves
    float*  bufRS = (float*)(smemh + 16896);            // [128 rows][2 nw]
    float*  bufCS = bufRS + 128 * 2;                    // [128 cols][2 mw]
    float*  bufD  = bufCS + 128 * 2;                    // MODE 2: denom[128]

    if (MODE == 1) __syncthreads();   // all warps done with mainloop smem before reuse

    if (MODE == 2) {
        // In-kernel denominator: thread r sums 32 partials for row m0+r.
        __syncthreads();              // mainloop smem reads done before bufD overwrite
        {
            const float* src = part + (size_t)(m0 + tid) * NTILE_N;
            float s = 0.0f;
            #pragma unroll
            for (int k2 = 0; k2 < NTILE_N; k2++) s += src[k2];
            bufD[tid] = s;
        }
        __syncthreads();
    }

    #pragma unroll
    for (int i = 0; i < 4; i++) {
        const int r0 = mw * 64 + i * 16 + g;
        const int r1 = r0 + 8;
        float sc0 = 1.0f, sc1 = 1.0f;
        if (MODE == 2) {
            sc0 = sc_glob / bufD[r0];
            sc1 = sc_glob / bufD[r1];
        }
        #pragma unroll
        for (int j = 0; j < 8; j++) {
            const int c0 = nw * 64 + j * 8 + 2 * q;
            float v00 = acc[i][j][0], v01 = acc[i][j][1];
            float v10 = acc[i][j][2], v11 = acc[i][j][3];
            if (MODE == 0) {
                const float b0 = __ldg(&bias[n0 + c0]);
                const float b1 = __ldg(&bias[n0 + c0 + 1]);
                __half2 h0 = __floats2half2_rn(v00 + b0, v01 + b1);
                __half2 h1 = __floats2half2_rn(v10 + b0, v11 + b1);
                *(__half2*)(C + (size_t)(m0 + r0) * ldC + n0 + c0) = h0;
                *(__half2*)(C + (size_t)(m0 + r1) * ldC + n0 + c0) = h1;
            } else if (MODE == 1) {
                __half2 h0 = __floats2half2_rn(__expf(v00 * 0.03125f), __expf(v01 * 0.03125f));
                __half2 h1 = __floats2half2_rn(__expf(v10 * 0.03125f), __expf(v11 * 0.03125f));
                *(__half2*)(C + (size_t)(m0 + r0) * ldC + n0 + c0) = h0;
                *(__half2*)(C + (size_t)(m0 + r1) * ldC + n0 + c0) = h1;
                bufT[(c0    ) * 132 + r0] = __low2half(h0);
                bufT[(c0 + 1) * 132 + r0] = __high2half(h0);
                bufT[(c0    ) * 132 + r1] = __low2half(h1);
                bufT[(c0 + 1) * 132 + r1] = __high2half(h1);
            } else {
                float2 f0 = make_float2(v00 * sc0, v01 * sc0);
                float2 f1 = make_float2(v10 * sc1, v11 * sc1);
                *(float2*)(Cf + (size_t)(m0 + r0) * ldC + n0 + c0) = f0;
                *(float2*)(Cf + (size_t)(m0 + r1) * ldC + n0 + c0) = f1;
            }
        }
    }

    if (MODE == 1) {
        // ---- partial softmax sums (recomputed unrounded exp from live acc) ----
        // row partials: this warp covers 64 cols; lanes sharing a row: xor 1,2 (q)
        #pragma unroll
        for (int i = 0; i < 4; i++) {
            float s0 = 0.0f, s1 = 0.0f;
            #pragma unroll
            for (int j = 0; j < 8; j++) {
                s0 += __expf(acc[i][j][0] * 0.03125f) + __expf(acc[i][j][1] * 0.03125f);
                s1 += __expf(acc[i][j][2] * 0.03125f) + __expf(acc[i][j][3] * 0.03125f);
            }
            s0 += __shfl_xor_sync(0xFFFFFFFFu, s0, 1);
            s0 += __shfl_xor_sync(0xFFFFFFFFu, s0, 2);
            s1 += __shfl_xor_sync(0xFFFFFFFFu, s1, 1);
            s1 += __shfl_xor_sync(0xFFFFFFFFu, s1, 2);
            if (q == 0) {
                bufRS[(mw * 64 + i * 16 + g) * 2 + nw]     = s0;
                bufRS[(mw * 64 + i * 16 + g + 8) * 2 + nw] = s1;
            }
        }
        // col partials: this warp covers 64 rows; lanes sharing a col: xor 4,8,16 (g)
        #pragma unroll
        for (int j = 0; j < 8; j++)
            #pragma unroll
            for (int h = 0; h < 2; h++) {
                float s = 0.0f;
                #pragma unroll
                for (int i = 0; i < 4; i++)
                    s += __expf(acc[i][j][h] * 0.03125f) + __expf(acc[i][j][h + 2] * 0.03125f);
                s += __shfl_xor_sync(0xFFFFFFFFu, s, 4);
                s += __shfl_xor_sync(0xFFFFFFFFu, s, 8);
                s += __shfl_xor_sync(0xFFFFFFFFu, s, 16);
                if (g == 0)
                    bufCS[(nw * 64 + j * 8 + 2 * q + h) * 2 + mw] = s;
            }

        __syncthreads();
        // coalesced P^T stores: warp w handles n-rows [w*32, w*32+32)
        for (int r = wid * 32; r < wid * 32 + 32; r++) {
            uint32_t* dst32 = (uint32_t*)(C2 + (size_t)(n0 + r) * ldC2 + m0);
            const uint32_t* src32 = (const uint32_t*)(bufT + r * 132);
            dst32[lid]      = src32[lid];
            dst32[lid + 32] = src32[lid + 32];
        }
        // global partial-sum stores (128 threads: each does one row AND one col)
        {
            const int r = tid;
            prs[(size_t)(m0 + r) * NTILE_N + blockIdx.x] = bufRS[r * 2] + bufRS[r * 2 + 1];
            pcs[(size_t)(n0 + r) * NTILE_M + blockIdx.y] = bufCS[r * 2] + bufCS[r * 2 + 1];
        }
    }
}

// ============================================================================
// Helper kernel: fused preprocessing, single launch.
// z=0: text  -> fp16 plane g_tx + transposed plane g_txT
// z=1: image -> fp16 plane g_im + transposed plane g_imT
// z=2: weights -> fp16 planes g_wt (by<16) / g_wi (16<=by<32); others idle.
// ============================================================================
__global__ void prep_k(const float* __restrict__ text,  __half* __restrict__ tx,
                       __half* __restrict__ txT,
                       const float* __restrict__ image, __half* __restrict__ im,
                       __half* __restrict__ imT,
                       const float* __restrict__ wtf, __half* __restrict__ wt,
                       const float* __restrict__ wif, __half* __restrict__ wi) {
    __shared__ float t[64][65];
    const int tx_ = threadIdx.x;    // 0..31
    const int ty_ = threadIdx.y;    // 0..7
    if (blockIdx.z == 2) {
        const int by = blockIdx.y;
        if (by >= 32) return;
        const float* in = (by < 16) ? wtf : wif;
        __half* out     = (by < 16) ? wt  : wi;
        const int y0 = (by & 15) * 64, x0 = blockIdx.x * 64;
        #pragma unroll
        for (int j = 0; j < 64; j += 8) {
            const int rl = ty_ + j;
            float2 v = *(const float2*)(in + (size_t)(y0 + rl) * DIM + x0 + 2 * tx_);
            *(__half2*)(out + (size_t)(y0 + rl) * DIM + x0 + 2 * tx_) = __floats2half2_rn(v.x, v.y);
        }
        return;
    }
    const float* in = blockIdx.z ? image : text;
    __half* out     = blockIdx.z ? im : tx;
    __half* outT    = blockIdx.z ? imT : txT;
    const int x0 = blockIdx.x * 64, y0 = blockIdx.y * 64;
    #pragma unroll
    for (int j = 0; j < 64; j += 8) {
        const int rl = ty_ + j;
        float2 v = *(const float2*)(in + (size_t)(y0 + rl) * DIM + x0 + 2 * tx_);
        t[rl][2 * tx_]     = v.x;
        t[rl][2 * tx_ + 1] = v.y;
        *(__half2*)(out + (size_t)(y0 + rl) * DIM + x0 + 2 * tx_) = __floats2half2_rn(v.x, v.y);
    }
    __syncthreads();
    #pragma unroll
    for (int j = 0; j < 64; j += 8) {
        const int cl = ty_ + j;
        __half2 hv = __floats2half2_rn(t[2 * tx_][cl], t[2 * tx_ + 1][cl]);
        *(__half2*)(outT + (size_t)(x0 + cl) * N_TOK + y0 + 2 * tx_) = hv;
    }
}

// ============================================================================
// Host launch
// ============================================================================
extern "C" void kernel_launch(void* const* d_in, const int* in_sizes, int n_in,
                              void* d_out, int out_size) {
    const float* text    = (const float*)d_in[0];
    const float* image   = (const float*)d_in[1];
    const float* w_text  = (const float*)d_in[2];
    const float* b_text  = (const float*)d_in[3];
    const float* w_image = (const float*)d_in[4];
    const float* b_image = (const float*)d_in[5];
    const float* s_TI    = (const float*)d_in[6];
    const float* s_IT    = (const float*)d_in[7];
    float* out = (float*)d_out;

    __half *tx, *im, *wt, *wi, *imT, *txT, *th, *ih, *P, *PT;
    float *prs, *pcs;
    cudaGetSymbolAddress((void**)&tx,  g_tx);
    cudaGetSymbolAddress((void**)&im,  g_im);
    cudaGetSymbolAddress((void**)&wt,  g_wt);
    cudaGetSymbolAddress((void**)&wi,  g_wi);
    cudaGetSymbolAddress((void**)&imT, g_imT);
    cudaGetSymbolAddress((void**)&txT, g_txT);
    cudaGetSymbolAddress((void**)&th,  g_t);
    cudaGetSymbolAddress((void**)&ih,  g_i);
    cudaGetSymbolAddress((void**)&P,   g_P);
    cudaGetSymbolAddress((void**)&PT,  g_PT);
    cudaGetSymbolAddress((void**)&prs, g_prs);
    cudaGetSymbolAddress((void**)&pcs, g_pcs);

    cudaFuncSetAttribute((const void*)gemm_h<0>, cudaFuncAttributeMaxDynamicSharedMemorySize, SMEM_H);
    cudaFuncSetAttribute((const void*)gemm_h<1>, cudaFuncAttributeMaxDynamicSharedMemorySize, SMEM_H);
    cudaFuncSetAttribute((const void*)gemm_h<2>, cudaFuncAttributeMaxDynamicSharedMemorySize, SMEM_H);

    // 1) fused preprocessing: conversions + transposes, single launch
    {
        dim3 blk(32, 8);
        dim3 grd(DIM / 64, N_TOK / 64, 3);
        prep_k<<<grd, blk>>>(text, tx, txT, image, im, imT, w_text, wt, w_image, wi);
    }
    // 2) projections merged:  t = text@wt^T+b_t (z=0),  i = image@wi^T+b_i (z=1)
    {
        dim3 grd(DIM / BN, N_TOK / BM, 2);
        gemm_h<0><<<grd, 128, SMEM_H>>>(tx, wt, im, wi, DIM, DIM, DIM,
                                        th, ih, DIM, nullptr, 0,
                                        nullptr, nullptr,
                                        b_text, b_image, nullptr, nullptr, nullptr, nullptr,
                                        nullptr, nullptr);
    }
    // 3) logits + exp:  P = exp((t @ i^T)/32),  PT = P^T, partial sums -> prs/pcs
    {
        dim3 grd(N_TOK / BN, N_TOK / BM, 1);
        gemm_h<1><<<grd, 128, SMEM_H>>>(th, ih, th, ih, DIM, DIM, DIM,
                                        P, P, N_TOK, PT, N_TOK,
                                        nullptr, nullptr,
                                        nullptr, nullptr, nullptr, nullptr, nullptr, nullptr,
                                        prs, pcs);
    }
    // 4) outputs merged (denoms computed in-kernel from prs/pcs):
    //    out1 = (P@image)*s_TI/rowsum (z=0), out2 = (PT@text)*s_IT/colsum (z=1)
    {
        dim3 grd(DIM / BN, N_TOK / BM, 2);
        gemm_h<2><<<grd, 128, SMEM_H>>>(P, imT, PT, txT, N_TOK, N_TOK, N_TOK,
                                        nullptr, nullptr, DIM, nullptr, 0,
                                        out, out + (size_t)N_TOK * DIM,
                                        nullptr, nullptr, prs, pcs, s_TI, s_IT,
                                        nullptr, nullptr);
    }
}